// round 1
// baseline (speedup 1.0000x reference)
#include <cuda_runtime.h>

// Problem constants (fixed by setup_inputs): B=4, N=M=8192, D=3
constexpr int Bn = 4;
constexpr int Nn = 8192;
constexpr int Mn = 8192;

constexpr int TC    = 512;   // target chunk staged in shared
constexpr int R     = 8;     // source rows per thread (register-resident)
constexpr int T     = 128;   // threads per block
constexpr int ST    = T * R; // 1024 source rows per block
constexpr int NWARP = T / 32;

// Scratch: row mins [0, B*N), col mins [B*N, 2*B*N). Stored as order-preserving uint keys.
__device__ unsigned g_minbuf[2 * Bn * Nn];

__device__ __forceinline__ unsigned fkey(float x) {
    unsigned u = __float_as_uint(x);
    return (u & 0x80000000u) ? ~u : (u | 0x80000000u);
}
__device__ __forceinline__ float funkey(unsigned k) {
    return (k & 0x80000000u) ? __uint_as_float(k & 0x7fffffffu)
                             : __uint_as_float(~k);
}

__global__ void init_minbuf() {
    int i = blockIdx.x * blockDim.x + threadIdx.x;
    g_minbuf[i] = 0xFFFFFFFFu;  // larger than any valid key
}

__global__ __launch_bounds__(T, 8)
void chamfer_main(const float* __restrict__ src, const float* __restrict__ tgt) {
    __shared__ float4 tsh[TC];          // target x,y,z,|t|^2
    __shared__ float  scolw[NWARP][TC]; // per-warp column mins of f

    const int tid  = threadIdx.x;
    const int lane = tid & 31;
    const int w    = tid >> 5;
    const int b    = blockIdx.z;
    const int s0   = blockIdx.y * ST;
    const int t0   = blockIdx.x * TC;

    // Stage target chunk into shared (SoA float4 with precomputed |t|^2)
    for (int i = tid; i < TC; i += T) {
        const float* p = tgt + ((size_t)b * Mn + t0 + i) * 3;
        float x = p[0], y = p[1], z = p[2];
        tsh[i] = make_float4(x, y, z, fmaf(x, x, fmaf(y, y, z * z)));
    }

    // Load this thread's R source points into registers
    float sx[R], sy[R], sz[R], sqs[R], emin[R];
    const float INF = __int_as_float(0x7f800000);
#pragma unroll
    for (int r = 0; r < R; r++) {
        int row = s0 + tid + r * T;
        const float* p = src + ((size_t)b * Nn + row) * 3;
        sx[r]  = p[0]; sy[r] = p[1]; sz[r] = p[2];
        sqs[r] = fmaf(sx[r], sx[r], fmaf(sy[r], sy[r], sz[r] * sz[r]));
        emin[r] = INF;
    }
    __syncthreads();

    // Main sweep: every thread visits every column; rows are private.
#pragma unroll 2
    for (int j = 0; j < TC; j++) {
        float4 t = tsh[j];  // broadcast LDS.128, conflict-free
        float fr[R];
#pragma unroll
        for (int r = 0; r < R; r++) {
            float c = fmaf(sx[r], t.x, fmaf(sy[r], t.y, sz[r] * t.z));
            float e = fmaf(c, -2.0f, t.w);     // FFMA-imm (rt=1)
            emin[r] = fminf(emin[r], e);
            fr[r]   = fmaf(c, -2.0f, sqs[r]);  // FFMA-imm (rt=1)
        }
        // Tree-min over this thread's rows (short dep chain)
#pragma unroll
        for (int s = R / 2; s > 0; s >>= 1)
#pragma unroll
            for (int r = 0; r < s; r++) fr[r] = fminf(fr[r], fr[r + s]);
        float fc = fr[0];
        // Warp reduce column min (latency hidden by multi-block occupancy)
#pragma unroll
        for (int o = 16; o > 0; o >>= 1)
            fc = fminf(fc, __shfl_xor_sync(0xffffffffu, fc, o));
        if (lane == 0) scolw[w][j] = fc;  // each warp visits j exactly once
    }
    __syncthreads();

    // Flush column mins: d2 = |t|^2 + min_r(|s|^2 - 2c)
    for (int j = tid; j < TC; j += T) {
        float m = fminf(fminf(scolw[0][j], scolw[1][j]),
                        fminf(scolw[2][j], scolw[3][j]));
        float d = tsh[j].w + m;
        atomicMin(&g_minbuf[Bn * Nn + b * Mn + t0 + j], fkey(d));
    }
    // Flush row mins: d2 = |s|^2 + min_j(|t|^2 - 2c)
#pragma unroll
    for (int r = 0; r < R; r++) {
        float d = sqs[r] + emin[r];
        atomicMin(&g_minbuf[b * Nn + s0 + tid + r * T], fkey(d));
    }
}

__global__ void final_reduce(float* out) {
    __shared__ float sh[512];
    int tid = threadIdx.x;
    float s = 0.0f;
    // Fixed traversal order per thread -> deterministic
    for (int i = tid; i < 2 * Bn * Nn; i += 512)
        s += funkey(g_minbuf[i]);
    sh[tid] = s;
    __syncthreads();
#pragma unroll
    for (int st = 256; st > 0; st >>= 1) {
        if (tid < st) sh[tid] += sh[tid + st];
        __syncthreads();
    }
    if (tid == 0)
        out[0] = sh[0] / (float)(Bn * Nn);  // (sum_rows+sum_cols)/(B*G)
}

extern "C" void kernel_launch(void* const* d_in, const int* in_sizes, int n_in,
                              void* d_out, int out_size) {
    const float* src = (const float*)d_in[0];  // (4, 8192, 3) fp32
    const float* tgt = (const float*)d_in[1];  // (4, 8192, 3) fp32
    float* out = (float*)d_out;

    init_minbuf<<<(2 * Bn * Nn) / 256, 256>>>();

    dim3 grid(Mn / TC, Nn / ST, Bn);  // (16, 8, 4) = 512 blocks
    chamfer_main<<<grid, T>>>(src, tgt);

    final_reduce<<<1, 512>>>(out);
}

// round 2
// speedup vs baseline: 2.2563x; 2.2563x over previous
#include <cuda_runtime.h>

// Problem constants (fixed by setup_inputs): B=4, N=M=8192, D=3
constexpr int Bn = 4;
constexpr int Nn = 8192;
constexpr int Mn = 8192;

constexpr int TC    = 256;   // target chunk staged in shared (halved -> 1024 blocks)
constexpr int R     = 8;     // source rows per thread (register-resident)
constexpr int T     = 128;   // threads per block
constexpr int ST    = T * R; // 1024 source rows per block
constexpr int NWARP = T / 32;

// Scratch: row mins [0, B*N), col mins [B*N, 2*B*N). Order-preserving uint keys.
__device__ unsigned g_minbuf[2 * Bn * Nn];

__device__ __forceinline__ unsigned fkey(float x) {
    unsigned u = __float_as_uint(x);
    // neg -> ~u ; pos -> u | 0x80000000  (single LOP3-able form)
    return u ^ ((unsigned)((int)u >> 31) | 0x80000000u);
}
__device__ __forceinline__ float funkey(unsigned k) {
    return (k & 0x80000000u) ? __uint_as_float(k & 0x7fffffffu)
                             : __uint_as_float(~k);
}

__global__ void init_minbuf() {
    int i = blockIdx.x * blockDim.x + threadIdx.x;
    g_minbuf[i] = 0xFFFFFFFFu;  // larger than any valid key
}

__global__ __launch_bounds__(T, 8)
void chamfer_main(const float* __restrict__ src, const float* __restrict__ tgt) {
    __shared__ float4   tsh[TC];          // target x,y,z,|t|^2
    __shared__ unsigned scolw[NWARP][TC]; // per-warp column min keys

    const int tid  = threadIdx.x;
    const int lane = tid & 31;
    const int w    = tid >> 5;
    const int b    = blockIdx.z;
    const int s0   = blockIdx.y * ST;
    const int t0   = blockIdx.x * TC;

    // Stage target chunk into shared (SoA float4 with precomputed |t|^2)
    for (int i = tid; i < TC; i += T) {
        const float* p = tgt + ((size_t)b * Mn + t0 + i) * 3;
        float x = p[0], y = p[1], z = p[2];
        tsh[i] = make_float4(x, y, z, fmaf(x, x, fmaf(y, y, z * z)));
    }

    // Load this thread's R source points into registers
    float sx[R], sy[R], sz[R], sqs[R], emin[R];
    const float INF = __int_as_float(0x7f800000);
#pragma unroll
    for (int r = 0; r < R; r++) {
        int row = s0 + tid + r * T;
        const float* p = src + ((size_t)b * Nn + row) * 3;
        sx[r]  = p[0]; sy[r] = p[1]; sz[r] = p[2];
        sqs[r] = fmaf(sx[r], sx[r], fmaf(sy[r], sy[r], sz[r] * sz[r]));
        emin[r] = INF;
    }
    __syncthreads();

    // Main sweep: every thread visits every column; rows are private.
#pragma unroll 4
    for (int j = 0; j < TC; j++) {
        float4 t = tsh[j];  // broadcast LDS.128, conflict-free
        float fr[R];
#pragma unroll
        for (int r = 0; r < R; r++) {
            float c = fmaf(sx[r], t.x, fmaf(sy[r], t.y, sz[r] * t.z));
            float e = fmaf(c, -2.0f, t.w);     // FFMA-imm (rt=1)
            emin[r] = fminf(emin[r], e);
            fr[r]   = fmaf(c, -2.0f, sqs[r]);  // FFMA-imm (rt=1)
        }
        // Tree-min over this thread's rows (alu pipe, parallel with fma)
#pragma unroll
        for (int s = R / 2; s > 0; s >>= 1)
#pragma unroll
            for (int r = 0; r < s; r++) fr[r] = fminf(fr[r], fr[r + s]);
        // Single-instruction warp reduction on order-preserving key
        unsigned k = __reduce_min_sync(0xffffffffu, fkey(fr[0]));
        if (lane == 0) scolw[w][j] = k;
    }
    __syncthreads();

    // Flush column mins: d2 = |t|^2 + min_r(|s|^2 - 2c)
    for (int j = tid; j < TC; j += T) {
        unsigned m = min(min(scolw[0][j], scolw[1][j]),
                         min(scolw[2][j], scolw[3][j]));
        float d = tsh[j].w + funkey(m);
        atomicMin(&g_minbuf[Bn * Nn + b * Mn + t0 + j], fkey(d));
    }
    // Flush row mins: d2 = |s|^2 + min_j(|t|^2 - 2c)
#pragma unroll
    for (int r = 0; r < R; r++) {
        float d = sqs[r] + emin[r];
        atomicMin(&g_minbuf[b * Nn + s0 + tid + r * T], fkey(d));
    }
}

__global__ void final_reduce(float* out) {
    __shared__ float sh[512];
    int tid = threadIdx.x;
    float s = 0.0f;
    // Vectorized, fixed traversal order -> deterministic
    const uint4* p4 = (const uint4*)g_minbuf;
    const int n4 = (2 * Bn * Nn) / 4;
#pragma unroll 4
    for (int i = tid; i < n4; i += 512) {
        uint4 v = p4[i];
        s += funkey(v.x) + funkey(v.y) + funkey(v.z) + funkey(v.w);
    }
    sh[tid] = s;
    __syncthreads();
#pragma unroll
    for (int st = 256; st > 0; st >>= 1) {
        if (tid < st) sh[tid] += sh[tid + st];
        __syncthreads();
    }
    if (tid == 0)
        out[0] = sh[0] / (float)(Bn * Nn);  // (sum_rows+sum_cols)/(B*G)
}

extern "C" void kernel_launch(void* const* d_in, const int* in_sizes, int n_in,
                              void* d_out, int out_size) {
    const float* src = (const float*)d_in[0];  // (4, 8192, 3) fp32
    const float* tgt = (const float*)d_in[1];  // (4, 8192, 3) fp32
    float* out = (float*)d_out;

    init_minbuf<<<(2 * Bn * Nn) / 256, 256>>>();

    dim3 grid(Mn / TC, Nn / ST, Bn);  // (32, 8, 4) = 1024 blocks
    chamfer_main<<<grid, T>>>(src, tgt);

    final_reduce<<<1, 512>>>(out);
}